// round 1
// baseline (speedup 1.0000x reference)
#include <cuda_runtime.h>
#include <math.h>

// Fused MoE router: logits = x @ W^T + b, top-2, masked softmax.
// M=16384 tokens, N=64 experts, K=4096. fp32 baseline (FFMA-bound ~280us predicted).
// Output layout assumption: float32 buffer, [idx (16384*2)] then [w (16384*2)].

#define BM 64
#define BK 32
#define LDT 68          // smem tile row stride in floats (pad 4 -> 272B = 17*16, LDS.128-aligned, conflict-free)
#define DIMS 4096
#define NEXP 64
#define NTOK 16384
#define NT (DIMS / BK)  // 128 K-steps

__global__ __launch_bounds__(256, 2)
void router_kernel(const float* __restrict__ x,
                   const float* __restrict__ W,
                   const float* __restrict__ bias,
                   float* __restrict__ out)
{
    // 2 double-buffered tiles: As[2][BK][LDT] + Ws[2][BK][LDT] = 8704 floats = 34816 B.
    // Reused as logits[64][65] in the epilogue.
    __shared__ __align__(16) float smem[8704];

    const int tid = threadIdx.x;
    const int bm  = blockIdx.x * BM;

    // Global->smem load mapping: thread loads float4 at (row lm / lm+32, cols lk..lk+3)
    const int lm = tid >> 3;          // 0..31
    const int lk = (tid & 7) << 2;    // 0,4,...,28

    // Compute mapping: 16x16 thread grid, 4x4 micro-tile
    const int tx = tid & 15;          // expert dim
    const int ty = tid >> 4;          // token dim

    const float* xg = x + (size_t)bm * DIMS;

    float acc[4][4];
#pragma unroll
    for (int j = 0; j < 4; j++)
#pragma unroll
        for (int i = 0; i < 4; i++) acc[j][i] = 0.0f;

    float* Asm = smem;                  // [2][BK][LDT]
    float* Wsm = smem + 2 * BK * LDT;   // [2][BK][LDT]

    // ---- prologue: load K-tile 0 into buffer 0 (stored transposed: [k][m]) ----
    {
        float4 a0 = *(const float4*)(xg + (size_t)lm * DIMS + lk);
        float4 a1 = *(const float4*)(xg + (size_t)(lm + 32) * DIMS + lk);
        float4 w0 = *(const float4*)(W + (size_t)lm * DIMS + lk);
        float4 w1 = *(const float4*)(W + (size_t)(lm + 32) * DIMS + lk);
        float* A  = Asm;
        float* Wt = Wsm;
        A[(lk+0)*LDT + lm]      = a0.x; A[(lk+1)*LDT + lm]      = a0.y;
        A[(lk+2)*LDT + lm]      = a0.z; A[(lk+3)*LDT + lm]      = a0.w;
        A[(lk+0)*LDT + lm + 32] = a1.x; A[(lk+1)*LDT + lm + 32] = a1.y;
        A[(lk+2)*LDT + lm + 32] = a1.z; A[(lk+3)*LDT + lm + 32] = a1.w;
        Wt[(lk+0)*LDT + lm]      = w0.x; Wt[(lk+1)*LDT + lm]      = w0.y;
        Wt[(lk+2)*LDT + lm]      = w0.z; Wt[(lk+3)*LDT + lm]      = w0.w;
        Wt[(lk+0)*LDT + lm + 32] = w1.x; Wt[(lk+1)*LDT + lm + 32] = w1.y;
        Wt[(lk+2)*LDT + lm + 32] = w1.z; Wt[(lk+3)*LDT + lm + 32] = w1.w;
    }
    __syncthreads();

    int buf = 0;
    for (int kt = 0; kt < NT; kt++) {
        float4 na0, na1, nw0, nw1;
        const bool hasnext = (kt + 1) < NT;
        if (hasnext) {
            const int ko = (kt + 1) * BK + lk;
            na0 = *(const float4*)(xg + (size_t)lm * DIMS + ko);
            na1 = *(const float4*)(xg + (size_t)(lm + 32) * DIMS + ko);
            nw0 = *(const float4*)(W + (size_t)lm * DIMS + ko);
            nw1 = *(const float4*)(W + (size_t)(lm + 32) * DIMS + ko);
        }

        const float* A  = Asm + buf * BK * LDT;
        const float* Wt = Wsm + buf * BK * LDT;
#pragma unroll
        for (int k = 0; k < BK; k++) {
            float4 av = *(const float4*)(A  + k * LDT + ty * 4);
            float4 wv = *(const float4*)(Wt + k * LDT + tx * 4);
            float a[4] = {av.x, av.y, av.z, av.w};
            float w[4] = {wv.x, wv.y, wv.z, wv.w};
#pragma unroll
            for (int j = 0; j < 4; j++)
#pragma unroll
                for (int i = 0; i < 4; i++)
                    acc[j][i] = fmaf(a[j], w[i], acc[j][i]);
        }

        if (hasnext) {
            float* An = Asm + (buf ^ 1) * BK * LDT;
            float* Wn = Wsm + (buf ^ 1) * BK * LDT;
            An[(lk+0)*LDT + lm]      = na0.x; An[(lk+1)*LDT + lm]      = na0.y;
            An[(lk+2)*LDT + lm]      = na0.z; An[(lk+3)*LDT + lm]      = na0.w;
            An[(lk+0)*LDT + lm + 32] = na1.x; An[(lk+1)*LDT + lm + 32] = na1.y;
            An[(lk+2)*LDT + lm + 32] = na1.z; An[(lk+3)*LDT + lm + 32] = na1.w;
            Wn[(lk+0)*LDT + lm]      = nw0.x; Wn[(lk+1)*LDT + lm]      = nw0.y;
            Wn[(lk+2)*LDT + lm]      = nw0.z; Wn[(lk+3)*LDT + lm]      = nw0.w;
            Wn[(lk+0)*LDT + lm + 32] = nw1.x; Wn[(lk+1)*LDT + lm + 32] = nw1.y;
            Wn[(lk+2)*LDT + lm + 32] = nw1.z; Wn[(lk+3)*LDT + lm + 32] = nw1.w;
            __syncthreads();
            buf ^= 1;
        }
    }
    __syncthreads();   // all reads of tiles done; smem free for reuse

    // ---- epilogue part 1: add bias, dump logits tile [64 tokens][65-stride] to smem ----
    float b4[4];
#pragma unroll
    for (int i = 0; i < 4; i++) b4[i] = bias[tx * 4 + i];
#pragma unroll
    for (int j = 0; j < 4; j++)
#pragma unroll
        for (int i = 0; i < 4; i++)
            smem[(ty * 4 + j) * 65 + tx * 4 + i] = acc[j][i] + b4[i];
    __syncthreads();

    // ---- epilogue part 2: per-token top-2 + softmax over {top1, top2} ----
    if (tid < BM) {
        const float* row = smem + tid * 65;
        float m1 = -INFINITY, m2 = -INFINITY;
        int i1 = 0, i2 = 0;
#pragma unroll
        for (int e = 0; e < NEXP; e++) {
            float v = row[e];
            if (v > m1)      { m2 = m1; i2 = i1; m1 = v; i1 = e; }
            else if (v > m2) { m2 = v;  i2 = e; }
        }
        // softmax over the two surviving logits (masked softmax zeroes the rest)
        float e21 = expf(m2 - m1);          // <= 1
        float w1v = 1.0f / (1.0f + e21);
        float w2v = e21 * w1v;

        const int gt = bm + tid;
        out[2 * gt + 0] = (float)i1;        // top_k_idx, already sorted desc by logit
        out[2 * gt + 1] = (float)i2;
        out[2 * NTOK + 2 * gt + 0] = w1v;   // top_k_w, sorted desc
        out[2 * NTOK + 2 * gt + 1] = w2v;
    }
}

extern "C" void kernel_launch(void* const* d_in, const int* in_sizes, int n_in,
                              void* d_out, int out_size)
{
    const float* x = (const float*)d_in[0];   // (4, 4096, 4096) f32
    const float* W = (const float*)d_in[1];   // (64, 4096) f32
    const float* b = (const float*)d_in[2];   // (64,) f32
    float* out = (float*)d_out;               // [idx 32768][w 32768] f32 (assumed)
    (void)in_sizes; (void)n_in; (void)out_size;

    router_kernel<<<NTOK / BM, 256>>>(x, W, b, out);
}

// round 6
// speedup vs baseline: 1.1252x; 1.1252x over previous
#include <cuda_runtime.h>
#include <cstdint>
#include <math.h>

// Fused MoE router: 1-pass tf32 mma.sync GEMM + top-2/softmax, with exact
// (double-float) fixup of tokens whose top-2/3 gaps are below threshold.
// M=16384 tokens, N=64 experts, K=4096. Output f32: [idx 32768][w 32768].

#define NTOK 16384
#define DIMS 4096
#define NEXP 64
#define BM   128
#define KC   64
#define NCH  (DIMS / KC)     // 64
#define LDA  68              // u32 row stride; frag banks (4r+q) conflict-free
#define GAP_THR 1e-2f
#define CAP  4096

// dynamic smem (bytes): As [2][128][68] u32, Ws [2][64][68] u32, bias[64] f32
#define SM_AS   0
#define SM_WS   69632
#define SM_BIAS 104448
#define SM_TOT  104704

__device__ int    g_cnt;
__device__ int    g_susp[CAP];
__device__ double g_logits[CAP][NEXP];

static __device__ __forceinline__ uint32_t tf32r(float x) {
    uint32_t u;
    asm("cvt.rna.tf32.f32 %0, %1;" : "=r"(u) : "f"(x));
    return u;
}

static __device__ __forceinline__ void mma8(float c[4],
                                            uint32_t a0, uint32_t a1, uint32_t a2, uint32_t a3,
                                            uint32_t b0, uint32_t b1) {
    asm volatile(
        "mma.sync.aligned.m16n8k8.row.col.f32.tf32.tf32.f32 "
        "{%0,%1,%2,%3}, {%4,%5,%6,%7}, {%8,%9}, {%0,%1,%2,%3};"
        : "+f"(c[0]), "+f"(c[1]), "+f"(c[2]), "+f"(c[3])
        : "r"(a0), "r"(a1), "r"(a2), "r"(a3), "r"(b0), "r"(b1));
}

// ---------------- kernel 0: reset suspect counter ----------------
__global__ void k_zero() { if (threadIdx.x == 0) g_cnt = 0; }

// ---------------- kernel 1: main GEMM + epilogue ----------------
__global__ __launch_bounds__(256, 1)
void k_main(const float* __restrict__ x,
            const float* __restrict__ W,
            const float* __restrict__ bias,
            float* __restrict__ out)
{
    extern __shared__ __align__(16) char smem[];
    uint32_t* As    = (uint32_t*)(smem + SM_AS);     // [2][128][LDA]
    uint32_t* Ws    = (uint32_t*)(smem + SM_WS);     // [2][64][LDA]
    float*    biasS = (float*)   (smem + SM_BIAS);

    const int tid  = threadIdx.x;
    const int wid  = tid >> 5;
    const int lane = tid & 31;
    const int wm   = wid & 3;          // M: wm*32, two m16 tiles
    const int wn   = wid >> 2;         // N: wn*32, four n8 tiles
    const int bm   = blockIdx.x * BM;

    if (tid < NEXP) biasS[tid] = bias[tid];

    // staging maps: A 2048 float4 (8/thread), W 1024 float4 (4/thread)
    const float* xg = x + (size_t)bm * DIMS;
    const float* agp[8]; int asm_off[8];
    const float* wgp[4]; int wsm_off[4];
#pragma unroll
    for (int j = 0; j < 8; j++) {
        int f = tid + 256 * j, row = f >> 4, c4 = (f & 15) << 2;
        agp[j]     = xg + (size_t)row * DIMS + c4;
        asm_off[j] = row * LDA + c4;
    }
#pragma unroll
    for (int j = 0; j < 4; j++) {
        int f = tid + 256 * j, row = f >> 4, c4 = (f & 15) << 2;
        wgp[j]     = W + (size_t)row * DIMS + c4;
        wsm_off[j] = row * LDA + c4;
    }

    const int aoff0 = (wm * 32 +      (lane >> 2)) * LDA + (lane & 3);
    const int aoff1 = (wm * 32 + 16 + (lane >> 2)) * LDA + (lane & 3);
    int boff[4];
#pragma unroll
    for (int nt = 0; nt < 4; nt++)
        boff[nt] = (wn * 32 + nt * 8 + (lane >> 2)) * LDA + (lane & 3);

    float acc[2][4][4];
#pragma unroll
    for (int mt = 0; mt < 2; mt++)
#pragma unroll
        for (int nt = 0; nt < 4; nt++)
#pragma unroll
            for (int q = 0; q < 4; q++) acc[mt][nt][q] = 0.0f;

    // prologue: chunk 0 -> smem buf 0 (tf32-converted)
    float4 avr[8], wvr[4];
#pragma unroll
    for (int j = 0; j < 8; j++) avr[j] = *(const float4*)(agp[j]);
#pragma unroll
    for (int j = 0; j < 4; j++) wvr[j] = *(const float4*)(wgp[j]);
#pragma unroll
    for (int j = 0; j < 8; j++) {
        uint4 u = make_uint4(tf32r(avr[j].x), tf32r(avr[j].y), tf32r(avr[j].z), tf32r(avr[j].w));
        *(uint4*)(As + asm_off[j]) = u;
    }
#pragma unroll
    for (int j = 0; j < 4; j++) {
        uint4 u = make_uint4(tf32r(wvr[j].x), tf32r(wvr[j].y), tf32r(wvr[j].z), tf32r(wvr[j].w));
        *(uint4*)(Ws + wsm_off[j]) = u;
    }
    __syncthreads();

    for (int i = 0; i < NCH; i++) {
        const int b = i & 1;
        const bool more = (i + 1) < NCH;
        if (more) {
            const int ko = (i + 1) * KC;
#pragma unroll
            for (int j = 0; j < 8; j++) avr[j] = *(const float4*)(agp[j] + ko);
#pragma unroll
            for (int j = 0; j < 4; j++) wvr[j] = *(const float4*)(wgp[j] + ko);
        }

        const uint32_t* Ab = As + b * (128 * LDA);
        const uint32_t* Wb = Ws + b * (64 * LDA);
#pragma unroll
        for (int ks = 0; ks < 8; ks++) {
            const int kc8 = ks * 8;
            uint32_t a00 = Ab[aoff0 + kc8],            a01 = Ab[aoff0 + 8 * LDA + kc8];
            uint32_t a02 = Ab[aoff0 + kc8 + 4],        a03 = Ab[aoff0 + 8 * LDA + kc8 + 4];
            uint32_t a10 = Ab[aoff1 + kc8],            a11 = Ab[aoff1 + 8 * LDA + kc8];
            uint32_t a12 = Ab[aoff1 + kc8 + 4],        a13 = Ab[aoff1 + 8 * LDA + kc8 + 4];
            uint32_t b0[4], b1[4];
#pragma unroll
            for (int nt = 0; nt < 4; nt++) {
                b0[nt] = Wb[boff[nt] + kc8];
                b1[nt] = Wb[boff[nt] + kc8 + 4];
            }
#pragma unroll
            for (int nt = 0; nt < 4; nt++) {
                mma8(acc[0][nt], a00, a01, a02, a03, b0[nt], b1[nt]);
                mma8(acc[1][nt], a10, a11, a12, a13, b0[nt], b1[nt]);
            }
        }

        if (more) {
            uint32_t* An = As + (b ^ 1) * (128 * LDA);
            uint32_t* Wn = Ws + (b ^ 1) * (64 * LDA);
#pragma unroll
            for (int j = 0; j < 8; j++) {
                uint4 u = make_uint4(tf32r(avr[j].x), tf32r(avr[j].y), tf32r(avr[j].z), tf32r(avr[j].w));
                *(uint4*)(An + asm_off[j]) = u;
            }
#pragma unroll
            for (int j = 0; j < 4; j++) {
                uint4 u = make_uint4(tf32r(wvr[j].x), tf32r(wvr[j].y), tf32r(wvr[j].z), tf32r(wvr[j].w));
                *(uint4*)(Wn + wsm_off[j]) = u;
            }
        }
        __syncthreads();
    }

    // epilogue: logits -> smem [128][66] (reuse As buffer 0 region)
    float* lg = (float*)(smem + SM_AS);
    {
        const int r0 = wm * 32 + (lane >> 2);
        const int c0 = wn * 32 + (lane & 3) * 2;
#pragma unroll
        for (int mt = 0; mt < 2; mt++)
#pragma unroll
            for (int nt = 0; nt < 4; nt++) {
                int r = r0 + mt * 16, c = c0 + nt * 8;
                *(float2*)(lg + r * 66 + c)       = make_float2(acc[mt][nt][0], acc[mt][nt][1]);
                *(float2*)(lg + (r + 8) * 66 + c) = make_float2(acc[mt][nt][2], acc[mt][nt][3]);
            }
    }
    __syncthreads();

    if (tid < BM) {
        const float* row = lg + tid * 66;
        float m1 = -INFINITY, m2 = -INFINITY, m3 = -INFINITY;
        int   i1 = 0, i2 = 0;
#pragma unroll
        for (int e = 0; e < NEXP; e++) {
            float v = row[e] + biasS[e];
            if (v > m1)      { m3 = m2; m2 = m1; i2 = i1; m1 = v; i1 = e; }
            else if (v > m2) { m3 = m2; m2 = v;  i2 = e; }
            else if (v > m3) { m3 = v; }
        }
        const int gt = bm + tid;
        if ((m1 - m2 < GAP_THR) || (m2 - m3 < GAP_THR)) {
            int slot = atomicAdd(&g_cnt, 1);
            if (slot < CAP) g_susp[slot] = gt;
        }
        float e21 = expf(m2 - m1);
        float w1v = 1.0f / (1.0f + e21);
        float w2v = e21 * w1v;
        out[2 * gt + 0] = (float)i1;
        out[2 * gt + 1] = (float)i2;
        out[2 * NTOK + 2 * gt + 0] = w1v;
        out[2 * NTOK + 2 * gt + 1] = w2v;
    }
}

// ---------------- kernel 2: exact logits for suspects (double-float dot) ----------------
static __device__ __forceinline__ void two_sum(float a, float b, float& s, float& e) {
    s = a + b;
    float v = s - a;
    e = (a - (s - v)) + (b - v);
}

__global__ __launch_bounds__(256)
void k_parts(const float* __restrict__ x,
             const float* __restrict__ W,
             const float* __restrict__ bias)
{
    __shared__ float xs[DIMS];
    const int tid = threadIdx.x;
    const int w   = tid >> 5;
    const int lane = tid & 31;
    const int cnt = min(g_cnt, CAP);

    for (int task = blockIdx.x; task < cnt * 4; task += gridDim.x) {
        const int s = task >> 2, p = task & 3;
        const int t = g_susp[s];

        const float4* xr = (const float4*)(x + (size_t)t * DIMS);
        for (int i = tid; i < DIMS / 4; i += 256) ((float4*)xs)[i] = xr[i];
        __syncthreads();

#pragma unroll
        for (int r = 0; r < 2; r++) {
            const int e = p * 16 + w * 2 + r;
            const float4* wr = (const float4*)(W + (size_t)e * DIMS);
            float hi = 0.0f, c = 0.0f;
#pragma unroll 4
            for (int it = 0; it < 32; it++) {
                float4 xv = ((const float4*)xs)[lane + 32 * it];
                float4 wv = wr[lane + 32 * it];
                float pr, pe, se;
                pr = xv.x * wv.x; pe = fmaf(xv.x, wv.x, -pr); two_sum(hi, pr, hi, se); c += se + pe;
                pr = xv.y * wv.y; pe = fmaf(xv.y, wv.y, -pr); two_sum(hi, pr, hi, se); c += se + pe;
                pr = xv.z * wv.z; pe = fmaf(xv.z, wv.z, -pr); two_sum(hi, pr, hi, se); c += se + pe;
                pr = xv.w * wv.w; pe = fmaf(xv.w, wv.w, -pr); two_sum(hi, pr, hi, se); c += se + pe;
            }
#pragma unroll
            for (int off = 16; off > 0; off >>= 1) {
                float oh = __shfl_down_sync(0xffffffffu, hi, off);
                float oc = __shfl_down_sync(0xffffffffu, c,  off);
                float ns, ne;
                two_sum(hi, oh, ns, ne);
                hi = ns; c = c + oc + ne;
            }
            if (lane == 0)
                g_logits[s][e] = (double)hi + (double)c + (double)bias[e];
        }
        __syncthreads();
    }
}

// ---------------- kernel 3: exact top-2 + softmax for suspects ----------------
__global__ __launch_bounds__(64)
void k_final(float* __restrict__ out)
{
    __shared__ double lg[NEXP];
    const int tid = threadIdx.x;
    const int cnt = min(g_cnt, CAP);

    for (int s = blockIdx.x; s < cnt; s += gridDim.x) {
        lg[tid] = g_logits[s][tid];
        __syncthreads();
        if (tid == 0) {
            const int t = g_susp[s];
            double m1 = -1e300, m2 = -1e300;
            int i1 = 0, i2 = 0;
            for (int e = 0; e < NEXP; e++) {
                double v = lg[e];
                if (v > m1)      { m2 = m1; i2 = i1; m1 = v; i1 = e; }
                else if (v > m2) { m2 = v;  i2 = e; }
            }
            double e21 = exp(m2 - m1);
            double w1v = 1.0 / (1.0 + e21);
            out[2 * t + 0] = (float)i1;
            out[2 * t + 1] = (float)i2;
            out[2 * NTOK + 2 * t + 0] = (float)w1v;
            out[2 * NTOK + 2 * t + 1] = (float)(e21 * w1v);
        }
        __syncthreads();
    }
}

extern "C" void kernel_launch(void* const* d_in, const int* in_sizes, int n_in,
                              void* d_out, int out_size)
{
    const float* x = (const float*)d_in[0];   // (4, 4096, 4096) f32
    const float* W = (const float*)d_in[1];   // (64, 4096) f32
    const float* b = (const float*)d_in[2];   // (64,) f32
    float* out = (float*)d_out;
    (void)in_sizes; (void)n_in; (void)out_size;

    cudaFuncSetAttribute(k_main, cudaFuncAttributeMaxDynamicSharedMemorySize, SM_TOT);

    k_zero<<<1, 32>>>();
    k_main<<<NTOK / BM, 256, SM_TOT>>>(x, W, b, out);
    k_parts<<<512, 256>>>(x, W, b);
    k_final<<<128, 64>>>(out);
}